// round 6
// baseline (speedup 1.0000x reference)
#include <cuda_runtime.h>
#include <cuda_bf16.h>
#include <cstdint>

// -------------------------------------------------------------------------
// CoralFocalLoss_MultiTask — fused single kernel.
//
// Per element (logit x, binary coral target tm):
//   loss = alpha(tm) * h(y),  y = tm ? x : -x,  alpha = tm ? 0.25 : 0.75
//   h(y) = sigmoid(-y)^2 * softplus(-y) = u^2 * (s - y)
//      t = e^y, a = 1+t, u^2 = rcp(a^2), s = log(a)
// Row loss scaled by class_weights[kl_t]. Outputs are means.
//
// 3 MUFU per logit (EX2, RCP, LG2); the RCP replaces a 6-instruction
// FMA-pipe Newton reciprocal+square, cutting issue load ~25%.
//
// Grid = 1184 blocks x 256 thr = one full-occupancy wave on 148 SMs.
// Finalize fused: last block (ticket) sums fixed-order partials.
// -------------------------------------------------------------------------

#define NBLOCKS 1184
#define NTHREADS 256

__device__ float        g_partials[NBLOCKS * 3];
__device__ unsigned int g_ticket = 0;   // atomicInc wraps to 0 each launch

__device__ __forceinline__ float rcp_approx(float x) {
    float r;
    asm("rcp.approx.f32 %0, %1;" : "=f"(r) : "f"(x));
    return r;
}

__device__ __forceinline__ float coral_term(float x, bool tm) {
    float y     = tm ? x : -x;
    float alpha = tm ? 0.25f : 0.75f;
    float t   = __expf(y);          // FMUL + MUFU.EX2
    float a   = 1.0f + t;           // FADD
    float usq = rcp_approx(a * a);  // FMUL + MUFU.RCP  (= sigmoid(-y)^2)
    float s   = __logf(a);          // MUFU.LG2 + FMUL
    return alpha * usq * (s - y);   // FADD + 2 FMUL
}

__global__ void __launch_bounds__(NTHREADS)
coral_fused_kernel(const float* __restrict__ kl_logits,
                   const float* __restrict__ jsnm_logits,
                   const float* __restrict__ jsnl_logits,
                   const float* __restrict__ class_weights,
                   const int*   __restrict__ kl_t,
                   const int*   __restrict__ jsnm_t,
                   const int*   __restrict__ jsnl_t,
                   float* __restrict__ out,
                   int n)
{
    __shared__ float s_w[5];
    __shared__ bool  s_is_last;
    if (threadIdx.x < 5) s_w[threadIdx.x] = class_weights[threadIdx.x];
    __syncthreads();

    float sum_kl = 0.0f, sum_m = 0.0f, sum_l = 0.0f;

    const int stride = gridDim.x * blockDim.x;
    for (int i = blockIdx.x * blockDim.x + threadIdx.x; i < n; i += stride) {
        int kt = kl_t[i];
        int mt = jsnm_t[i];
        int lt = jsnl_t[i];
        float w = s_w[kt];

        float4 q = reinterpret_cast<const float4*>(kl_logits)[i];
        float rk = coral_term(q.x, 0 < kt)
                 + coral_term(q.y, 1 < kt)
                 + coral_term(q.z, 2 < kt)
                 + coral_term(q.w, 3 < kt);
        sum_kl += w * rk;

        const float* pm = jsnm_logits + 3 * (size_t)i;
        float rm = coral_term(pm[0], 0 < mt)
                 + coral_term(pm[1], 1 < mt)
                 + coral_term(pm[2], 2 < mt);
        sum_m += w * rm;

        const float* pl = jsnl_logits + 3 * (size_t)i;
        float rl = coral_term(pl[0], 0 < lt)
                 + coral_term(pl[1], 1 < lt)
                 + coral_term(pl[2], 2 < lt);
        sum_l += w * rl;
    }

    // -------- block reduction (deterministic) --------
    const unsigned FULL = 0xFFFFFFFFu;
    #pragma unroll
    for (int o = 16; o > 0; o >>= 1) {
        sum_kl += __shfl_down_sync(FULL, sum_kl, o);
        sum_m  += __shfl_down_sync(FULL, sum_m,  o);
        sum_l  += __shfl_down_sync(FULL, sum_l,  o);
    }

    __shared__ float s_red[3][NTHREADS / 32];
    int wid = threadIdx.x >> 5;
    int lid = threadIdx.x & 31;
    if (lid == 0) {
        s_red[0][wid] = sum_kl;
        s_red[1][wid] = sum_m;
        s_red[2][wid] = sum_l;
    }
    __syncthreads();

    if (threadIdx.x == 0) {
        float v0 = 0.0f, v1 = 0.0f, v2 = 0.0f;
        #pragma unroll
        for (int i = 0; i < NTHREADS / 32; i++) {
            v0 += s_red[0][i];
            v1 += s_red[1][i];
            v2 += s_red[2][i];
        }
        g_partials[blockIdx.x * 3 + 0] = v0;
        g_partials[blockIdx.x * 3 + 1] = v1;
        g_partials[blockIdx.x * 3 + 2] = v2;
        __threadfence();
        unsigned t = atomicInc(&g_ticket, gridDim.x - 1);
        s_is_last = (t == gridDim.x - 1);
    }
    __syncthreads();

    // -------- last block to arrive finalizes (fixed-order, deterministic) --------
    if (s_is_last) {
        float v0 = 0.0f, v1 = 0.0f, v2 = 0.0f;
        for (int i = threadIdx.x; i < NBLOCKS; i += NTHREADS) {
            v0 += g_partials[i * 3 + 0];
            v1 += g_partials[i * 3 + 1];
            v2 += g_partials[i * 3 + 2];
        }
        #pragma unroll
        for (int o = 16; o > 0; o >>= 1) {
            v0 += __shfl_down_sync(FULL, v0, o);
            v1 += __shfl_down_sync(FULL, v1, o);
            v2 += __shfl_down_sync(FULL, v2, o);
        }
        if (lid == 0) {
            s_red[0][wid] = v0;
            s_red[1][wid] = v1;
            s_red[2][wid] = v2;
        }
        __syncthreads();
        if (threadIdx.x == 0) {
            float t0 = 0.0f, t1 = 0.0f, t2 = 0.0f;
            #pragma unroll
            for (int i = 0; i < NTHREADS / 32; i++) {
                t0 += s_red[0][i];
                t1 += s_red[1][i];
                t2 += s_red[2][i];
            }
            float fn = (float)n;
            float l_kl   = t0 / (4.0f * fn);
            float l_jsnm = t1 / (3.0f * fn);
            float l_jsnl = t2 / (3.0f * fn);
            out[0] = (l_kl + l_jsnm + l_jsnl) * (1.0f / 3.0f);
            out[1] = l_kl;
            out[2] = l_jsnm;
            out[3] = l_jsnl;
        }
    }
}

extern "C" void kernel_launch(void* const* d_in, const int* in_sizes, int n_in,
                              void* d_out, int out_size)
{
    const float* kl_logits     = (const float*)d_in[0];
    const float* jsnm_logits   = (const float*)d_in[1];
    const float* jsnl_logits   = (const float*)d_in[2];
    const float* class_weights = (const float*)d_in[3];
    const int*   kl_t          = (const int*)d_in[4];
    const int*   jsnm_t        = (const int*)d_in[5];
    const int*   jsnl_t        = (const int*)d_in[6];

    int n = in_sizes[4];  // N samples (kl_t element count)

    coral_fused_kernel<<<NBLOCKS, NTHREADS>>>(
        kl_logits, jsnm_logits, jsnl_logits, class_weights,
        kl_t, jsnm_t, jsnl_t, (float*)d_out, n);
}

// round 7
// speedup vs baseline: 1.0766x; 1.0766x over previous
#include <cuda_runtime.h>
#include <cuda_bf16.h>
#include <cstdint>

// -------------------------------------------------------------------------
// CoralFocalLoss_MultiTask — packed f32x2 body + sign LUTs.
//
// Per logit x with coral target tm:
//   y = s*x (s=+1 if tm else -1), alpha = 0.5 - 0.25*s
//   loss = alpha * sigmoid(-y)^2 * softplus(-y) = alpha * u^2 * (ln(a) - y)
//   t = exp(y) = ex2(x * s*log2e), a = 1+t, u = 1/a (bit-trick + 2 Newton)
//
// 10 logits/sample processed as 5 f32x2 pairs: (kl0,kl1)(kl2,kl3)(m0,m1)
// (l0,l1)(m2,l2). Packed fma-pipe math via inline PTX {mul,add,fma}.rn.f32x2
// (ptxas never emits these from C++). EX2/LG2 remain scalar MUFU (2/logit —
// measured to be the hard floor; R6 proved +1 MUFU/logit costs +3.7us).
//
// Newton without negation (f32x2 has no neg modifier):
//   d1 = a*u0 - 2 = -e1 ; v = u0*d1 = -u1
//   d2 = a*v + 2 =  e2 ; w = v*d2  = -u2 ; u2^2 = w*w  (sign cancels)
//
// Sign LUTs in shared replace per-logit ISETP/SELP: per target value store
// packed {sign*log2e} and {-sign}; alpha = fma(-S, 0.25, 0.5); w stored
// pre-packed {w,w}.
//
// Structure: main kernel -> per-block partials (fixed order) -> tiny
// finalize kernel (measured faster than in-kernel ticket epilogue).
// -------------------------------------------------------------------------

#define NBLOCKS 1184
#define NTHREADS 256

typedef unsigned long long u64;

__device__ float g_partials[NBLOCKS * 3];

// ---- packed f32x2 helpers --------------------------------------------------
__device__ __forceinline__ u64 pk(float lo, float hi) {
    u64 r; asm("mov.b64 %0, {%1, %2};" : "=l"(r) : "f"(lo), "f"(hi)); return r;
}
__device__ __forceinline__ void upk(u64 v, float& lo, float& hi) {
    asm("mov.b64 {%0, %1}, %2;" : "=f"(lo), "=f"(hi) : "l"(v));
}
__device__ __forceinline__ u64 mul2(u64 a, u64 b) {
    u64 r; asm("mul.rn.f32x2 %0, %1, %2;" : "=l"(r) : "l"(a), "l"(b)); return r;
}
__device__ __forceinline__ u64 add2(u64 a, u64 b) {
    u64 r; asm("add.rn.f32x2 %0, %1, %2;" : "=l"(r) : "l"(a), "l"(b)); return r;
}
__device__ __forceinline__ u64 fma2(u64 a, u64 b, u64 c) {
    u64 r; asm("fma.rn.f32x2 %0, %1, %2, %3;" : "=l"(r) : "l"(a), "l"(b), "l"(c)); return r;
}
__device__ __forceinline__ float ex2a(float x) {
    float r; asm("ex2.approx.f32 %0, %1;" : "=f"(r) : "f"(x)); return r;
}
__device__ __forceinline__ float lg2a(float x) {
    float r; asm("lg2.approx.f32 %0, %1;" : "=f"(r) : "f"(x)); return r;
}

// two logits packed in X; SL = packed sign*log2e; NS = packed -sign.
// returns packed alpha*u^2*(ln a - y), unweighted.
__device__ __forceinline__ u64 coral_pair(u64 X, u64 SL, u64 NS,
                                          u64 C_M2, u64 C_P2,
                                          u64 C_LN22, u64 C_Q2, u64 C_H2)
{
    u64 Z = mul2(X, SL);                   // z = y*log2e (packed)
    float z0, z1; upk(Z, z0, z1);
    float t0 = ex2a(z0), t1 = ex2a(z1);    // t = e^y       (2 MUFU)
    float a0 = t0 + 1.0f, a1 = t1 + 1.0f;
    float u0 = __int_as_float(0x7EF311C3 - __float_as_int(a0));
    float u1 = __int_as_float(0x7EF311C3 - __float_as_int(a1));
    u64 U = pk(u0, u1);
    u64 A = pk(a0, a1);
    u64 d1 = fma2(A, U, C_M2);             // a*u - 2  = -e1
    u64 V  = mul2(U, d1);                  // -u1
    u64 d2 = fma2(A, V, C_P2);             // a*v + 2  =  e2
    u64 W  = mul2(V, d2);                  // -u2
    u64 USQ = mul2(W, W);                  // u2^2
    float g0 = lg2a(a0), g1 = lg2a(a1);    // lg2(a)        (2 MUFU)
    u64 G  = pk(g0, g1);
    u64 NY = mul2(X, NS);                  // -y
    u64 SP = fma2(G, C_LN22, NY);          // ln(a) - y
    u64 AL = fma2(NS, C_Q2, C_H2);         // 0.5 + 0.25*(-s)
    return mul2(mul2(USQ, SP), AL);
}

__global__ void __launch_bounds__(NTHREADS, 4)
coral_main_kernel(const float* __restrict__ kl_logits,
                  const float* __restrict__ jsnm_logits,
                  const float* __restrict__ jsnl_logits,
                  const float* __restrict__ class_weights,
                  const int*   __restrict__ kl_t,
                  const int*   __restrict__ jsnm_t,
                  const int*   __restrict__ jsnl_t,
                  int n)
{
    const float L2E = 1.44269504088896340736f;

    __shared__ ulonglong2 s_kl_sl[5];   // {SL01, SL23} per kt
    __shared__ ulonglong2 s_kl_ns[5];   // {NS01, NS23} per kt
    __shared__ u64   s_3_sl01[4];       // 3-logit tasks: pair (0,1)
    __shared__ u64   s_3_ns01[4];
    __shared__ float s_3_sl2[4];        // 3-logit tasks: logit 2 (scalar)
    __shared__ float s_3_ns2[4];
    __shared__ u64   s_w2[5];           // {w, w}

    int tid = threadIdx.x;
    if (tid < 5) {
        float w = class_weights[tid];
        s_w2[tid] = pk(w, w);
        float s0 = (0 < tid) ? 1.0f : -1.0f;
        float s1 = (1 < tid) ? 1.0f : -1.0f;
        float s2 = (2 < tid) ? 1.0f : -1.0f;
        float s3 = (3 < tid) ? 1.0f : -1.0f;
        ulonglong2 sl; sl.x = pk(s0 * L2E, s1 * L2E); sl.y = pk(s2 * L2E, s3 * L2E);
        ulonglong2 ns; ns.x = pk(-s0, -s1);           ns.y = pk(-s2, -s3);
        s_kl_sl[tid] = sl;
        s_kl_ns[tid] = ns;
    }
    if (tid < 4) {
        float s0 = (0 < tid) ? 1.0f : -1.0f;
        float s1 = (1 < tid) ? 1.0f : -1.0f;
        float s2 = (2 < tid) ? 1.0f : -1.0f;
        s_3_sl01[tid] = pk(s0 * L2E, s1 * L2E);
        s_3_ns01[tid] = pk(-s0, -s1);
        s_3_sl2[tid]  = s2 * L2E;
        s_3_ns2[tid]  = -s2;
    }
    __syncthreads();

    const u64 C_M2   = pk(-2.0f, -2.0f);
    const u64 C_P2   = pk( 2.0f,  2.0f);
    const u64 C_LN22 = pk(0.69314718055994530942f, 0.69314718055994530942f);
    const u64 C_Q2   = pk(0.25f, 0.25f);
    const u64 C_H2   = pk(0.5f, 0.5f);
    const u64 ZERO2  = 0ULL;

    u64 acc_kl = ZERO2;   // lanes: both -> sum_kl
    u64 acc_m  = ZERO2;   // lanes: both -> sum_m  (jsnm logits 0,1)
    u64 acc_l  = ZERO2;   // lanes: both -> sum_l  (jsnl logits 0,1)
    u64 acc_ml = ZERO2;   // lane0 -> sum_m (jsnm logit 2), lane1 -> sum_l (jsnl logit 2)

    const int stride = gridDim.x * blockDim.x;
    for (int i = blockIdx.x * blockDim.x + threadIdx.x; i < n; i += stride) {
        int kt = kl_t[i];
        int mt = jsnm_t[i];
        int lt = jsnl_t[i];
        u64 W2 = s_w2[kt];

        // ---- kl: 4 logits = 2 packed pairs (one 16B load) ----
        ulonglong2 X  = reinterpret_cast<const ulonglong2*>(kl_logits)[i];
        ulonglong2 SL = s_kl_sl[kt];
        ulonglong2 NS = s_kl_ns[kt];
        u64 r0 = coral_pair(X.x, SL.x, NS.x, C_M2, C_P2, C_LN22, C_Q2, C_H2);
        u64 r1 = coral_pair(X.y, SL.y, NS.y, C_M2, C_P2, C_LN22, C_Q2, C_H2);
        acc_kl = fma2(add2(r0, r1), W2, acc_kl);

        // ---- jsnm / jsnl rows (3 floats each, scalar loads) ----
        const float* pm = jsnm_logits + 3 * (size_t)i;
        float m0 = pm[0], m1 = pm[1], m2 = pm[2];
        const float* pl = jsnl_logits + 3 * (size_t)i;
        float l0 = pl[0], l1 = pl[1], l2 = pl[2];

        u64 rm = coral_pair(pk(m0, m1), s_3_sl01[mt], s_3_ns01[mt],
                            C_M2, C_P2, C_LN22, C_Q2, C_H2);
        acc_m = fma2(rm, W2, acc_m);

        u64 rl = coral_pair(pk(l0, l1), s_3_sl01[lt], s_3_ns01[lt],
                            C_M2, C_P2, C_LN22, C_Q2, C_H2);
        acc_l = fma2(rl, W2, acc_l);

        // cross-stream pair: (jsnm logit2, jsnl logit2)
        u64 rml = coral_pair(pk(m2, l2),
                             pk(s_3_sl2[mt], s_3_sl2[lt]),
                             pk(s_3_ns2[mt], s_3_ns2[lt]),
                             C_M2, C_P2, C_LN22, C_Q2, C_H2);
        acc_ml = fma2(rml, W2, acc_ml);
    }

    // ---- split packed accumulators into the three stream sums ----
    float klo, khi, mlo, mhi, llo, lhi, xlo, xhi;
    upk(acc_kl, klo, khi);
    upk(acc_m,  mlo, mhi);
    upk(acc_l,  llo, lhi);
    upk(acc_ml, xlo, xhi);
    float sum_kl = klo + khi;
    float sum_m  = mlo + mhi + xlo;
    float sum_l  = llo + lhi + xhi;

    // ---- deterministic block reduction ----
    const unsigned FULL = 0xFFFFFFFFu;
    #pragma unroll
    for (int o = 16; o > 0; o >>= 1) {
        sum_kl += __shfl_down_sync(FULL, sum_kl, o);
        sum_m  += __shfl_down_sync(FULL, sum_m,  o);
        sum_l  += __shfl_down_sync(FULL, sum_l,  o);
    }

    __shared__ float s_red[3][NTHREADS / 32];
    int wid = threadIdx.x >> 5;
    int lid = threadIdx.x & 31;
    if (lid == 0) {
        s_red[0][wid] = sum_kl;
        s_red[1][wid] = sum_m;
        s_red[2][wid] = sum_l;
    }
    __syncthreads();

    if (threadIdx.x == 0) {
        float v0 = 0.0f, v1 = 0.0f, v2 = 0.0f;
        #pragma unroll
        for (int i2 = 0; i2 < NTHREADS / 32; i2++) {
            v0 += s_red[0][i2];
            v1 += s_red[1][i2];
            v2 += s_red[2][i2];
        }
        g_partials[blockIdx.x * 3 + 0] = v0;
        g_partials[blockIdx.x * 3 + 1] = v1;
        g_partials[blockIdx.x * 3 + 2] = v2;
    }
}

__global__ void __launch_bounds__(NTHREADS)
coral_finalize_kernel(float* __restrict__ out, int nblocks, int n)
{
    float v0 = 0.0f, v1 = 0.0f, v2 = 0.0f;
    for (int i = threadIdx.x; i < nblocks; i += NTHREADS) {
        v0 += g_partials[i * 3 + 0];
        v1 += g_partials[i * 3 + 1];
        v2 += g_partials[i * 3 + 2];
    }
    const unsigned FULL = 0xFFFFFFFFu;
    #pragma unroll
    for (int o = 16; o > 0; o >>= 1) {
        v0 += __shfl_down_sync(FULL, v0, o);
        v1 += __shfl_down_sync(FULL, v1, o);
        v2 += __shfl_down_sync(FULL, v2, o);
    }
    __shared__ float s_red[3][NTHREADS / 32];
    int wid = threadIdx.x >> 5;
    int lid = threadIdx.x & 31;
    if (lid == 0) {
        s_red[0][wid] = v0;
        s_red[1][wid] = v1;
        s_red[2][wid] = v2;
    }
    __syncthreads();
    if (threadIdx.x == 0) {
        float t0 = 0.0f, t1 = 0.0f, t2 = 0.0f;
        #pragma unroll
        for (int i = 0; i < NTHREADS / 32; i++) {
            t0 += s_red[0][i];
            t1 += s_red[1][i];
            t2 += s_red[2][i];
        }
        float fn = (float)n;
        float l_kl   = t0 / (4.0f * fn);
        float l_jsnm = t1 / (3.0f * fn);
        float l_jsnl = t2 / (3.0f * fn);
        out[0] = (l_kl + l_jsnm + l_jsnl) * (1.0f / 3.0f);
        out[1] = l_kl;
        out[2] = l_jsnm;
        out[3] = l_jsnl;
    }
}

extern "C" void kernel_launch(void* const* d_in, const int* in_sizes, int n_in,
                              void* d_out, int out_size)
{
    const float* kl_logits     = (const float*)d_in[0];
    const float* jsnm_logits   = (const float*)d_in[1];
    const float* jsnl_logits   = (const float*)d_in[2];
    const float* class_weights = (const float*)d_in[3];
    const int*   kl_t          = (const int*)d_in[4];
    const int*   jsnm_t        = (const int*)d_in[5];
    const int*   jsnl_t        = (const int*)d_in[6];

    int n = in_sizes[4];  // N samples (kl_t element count)

    coral_main_kernel<<<NBLOCKS, NTHREADS>>>(
        kl_logits, jsnm_logits, jsnl_logits, class_weights,
        kl_t, jsnm_t, jsnl_t, n);

    coral_finalize_kernel<<<1, NTHREADS>>>((float*)d_out, NBLOCKS, n);
}